// round 1
// baseline (speedup 1.0000x reference)
#include <cuda_runtime.h>
#include <math.h>

#define NB 64
#define ND 2048
#define NA 256
#define NR 64

// scratch (device globals: allocation-free rule)
__device__ float g_scale[NB];
__device__ __align__(16) float g_Q[NB*NA*NR];
__device__ __align__(16) float g_K[NB*NA*NR];
__device__ __align__(16) float g_V[NB*NA*NR];
__device__ __align__(16) float g_O[NB*NA*NR];
__device__ __align__(16) float g_M[NB*NA*NR];

// ---------------- scale: numN = count(L[b,0,:] >= 1) + 1 ; scale = sqrt ----------------
__global__ void k_scale(const float* __restrict__ L) {
    int b = blockIdx.x;
    int tid = threadIdx.x;
    float c = (L[b * 2 * NA + tid] >= 1.0f) ? 1.0f : 0.0f;
    __shared__ float red[8];
    for (int o = 16; o > 0; o >>= 1) c += __shfl_down_sync(0xffffffffu, c, o);
    if ((tid & 31) == 0) red[tid >> 5] = c;
    __syncthreads();
    if (tid == 0) {
        float t = 0.f;
        #pragma unroll
        for (int i = 0; i < 8; i++) t += red[i];
        g_scale[b] = sqrtf(t + 1.0f);
    }
}

// ---------------- layer-1 QKV GEMM: Z[r,n] = W[r,:] @ x[b,:,n], sigmoid, store (b,n,r) ----------------
// grid (2 ntiles, 64 b, 3 qkv), 256 threads, 64x128 tile, 4x8 microtile, k-step 16
__global__ void __launch_bounds__(256) k_gemm1(const float* __restrict__ x,
                                               const float* __restrict__ Aq,
                                               const float* __restrict__ Ak,
                                               const float* __restrict__ Av) {
    __shared__ float Wt[16][68];    // [k][r], padded for float4-aligned rows
    __shared__ float Xt[16][132];   // [k][n], padded
    __shared__ float eps[64][133];  // epilogue transpose buffer (conflict-free: 133%32=5)

    int b = blockIdx.y;
    int nbase = blockIdx.x << 7;     // 0 or 128
    int z = blockIdx.z;
    const float* W = (z == 0) ? Aq : ((z == 1) ? Ak : Av);
    float* Out = (z == 0) ? g_Q : ((z == 1) ? g_K : g_V);

    int tid = threadIdx.x;
    int tx = tid & 15, ty = tid >> 4;

    float acc[4][8];
    #pragma unroll
    for (int i = 0; i < 4; i++)
        #pragma unroll
        for (int j = 0; j < 8; j++) acc[i][j] = 0.f;

    const float* xb = x + (size_t)b * ND * NA;

    for (int k0 = 0; k0 < ND; k0 += 16) {
        // load W tile: 64 r x 16 k = 256 float4, one per thread, transpose into Wt
        {
            int r = tid >> 2;
            int kq = (tid & 3) << 2;
            float4 w4 = *(const float4*)&W[r * ND + k0 + kq];
            Wt[kq + 0][r] = w4.x; Wt[kq + 1][r] = w4.y;
            Wt[kq + 2][r] = w4.z; Wt[kq + 3][r] = w4.w;
        }
        // load X tile: 16 k x 128 n = 512 float4, two per thread
        #pragma unroll
        for (int i = 0; i < 2; i++) {
            int e = tid + (i << 8);
            int kk = e >> 5;
            int n4 = (e & 31) << 2;
            float4 v = *(const float4*)&xb[(size_t)(k0 + kk) * NA + nbase + n4];
            *(float4*)&Xt[kk][n4] = v;
        }
        __syncthreads();
        #pragma unroll
        for (int kk = 0; kk < 16; kk++) {
            float4 a4 = *(const float4*)&Wt[kk][ty << 2];
            float4 b0 = *(const float4*)&Xt[kk][tx << 3];
            float4 b1 = *(const float4*)&Xt[kk][(tx << 3) + 4];
            float av[4] = {a4.x, a4.y, a4.z, a4.w};
            float bv[8] = {b0.x, b0.y, b0.z, b0.w, b1.x, b1.y, b1.z, b1.w};
            #pragma unroll
            for (int i = 0; i < 4; i++)
                #pragma unroll
                for (int j = 0; j < 8; j++) acc[i][j] += av[i] * bv[j];
        }
        __syncthreads();
    }

    // epilogue: sigmoid + transpose-store into (b, n, r) layout, coalesced
    #pragma unroll
    for (int i = 0; i < 4; i++)
        #pragma unroll
        for (int j = 0; j < 8; j++) {
            float v = acc[i][j];
            eps[(ty << 2) + i][(tx << 3) + j] = __frcp_rn(1.0f + __expf(-v));
        }
    __syncthreads();
    float* ob = Out + ((size_t)b * NA + nbase) * NR;
    #pragma unroll
    for (int e = tid; e < 64 * 128; e += 256) {
        int r = e & 63, nl = e >> 6;
        ob[nl * NR + r] = eps[r][nl];
    }
}

// ---------------- attention: per (b, n-half) block, m split across thread halves ----------------
// logits u = Q[n,:].K[m,:] in [0,64]; softmax shift with constant C = 64 (pre-scale) => single pass
#define ATTN_SMEM ((16384 + 16384 + 128 * 65 + 128) * 4)
__global__ void __launch_bounds__(256, 1) k_attn() {
    extern __shared__ float sm[];
    float* Ks = sm;                     // [256][64]
    float* Vs = sm + 16384;             // [256][64]
    float* xa = sm + 32768;             // [128][65] partial acc exchange
    float* sex = xa + 128 * 65;         // [128]

    int b = blockIdx.y;
    int nbase = blockIdx.x << 7;
    int tid = threadIdx.x;
    int nl = tid & 127;
    int mh = tid >> 7;
    size_t base = (size_t)b * (NA * NR);

    const float4* Kg = (const float4*)(g_K + base);
    const float4* Vg = (const float4*)(g_V + base);
    float4* Ks4 = (float4*)Ks;
    float4* Vs4 = (float4*)Vs;
    #pragma unroll
    for (int i = 0; i < 16; i++) {
        int e = tid + (i << 8);
        Ks4[e] = Kg[e];
        Vs4[e] = Vg[e];
    }
    float q[64];
    {
        const float4* qg = (const float4*)(g_Q + base + (size_t)(nbase + nl) * NR);
        #pragma unroll
        for (int i = 0; i < 16; i++) {
            float4 v = qg[i];
            q[i * 4] = v.x; q[i * 4 + 1] = v.y; q[i * 4 + 2] = v.z; q[i * 4 + 3] = v.w;
        }
    }
    float invs = __frcp_rn(g_scale[b]);
    __syncthreads();

    float acc[64];
    #pragma unroll
    for (int i = 0; i < 64; i++) acc[i] = 0.f;
    float se = 0.f;

    int mbase = mh << 7;
    for (int m = mbase; m < mbase + 128; m++) {
        const float4* kr = (const float4*)(Ks + m * NR);
        float u = 0.f;
        #pragma unroll
        for (int i = 0; i < 16; i++) {
            float4 kv = kr[i];
            u += q[i * 4] * kv.x + q[i * 4 + 1] * kv.y + q[i * 4 + 2] * kv.z + q[i * 4 + 3] * kv.w;
        }
        float p = __expf((u - 64.0f) * invs);
        se += p;
        const float4* vr = (const float4*)(Vs + m * NR);
        #pragma unroll
        for (int i = 0; i < 16; i++) {
            float4 vv = vr[i];
            acc[i * 4]     += p * vv.x;
            acc[i * 4 + 1] += p * vv.y;
            acc[i * 4 + 2] += p * vv.z;
            acc[i * 4 + 3] += p * vv.w;
        }
    }

    if (mh) {
        #pragma unroll
        for (int i = 0; i < 64; i++) xa[nl * 65 + i] = acc[i];
        sex[nl] = se;
    }
    __syncthreads();
    if (!mh) {
        se += sex[nl];
        float inv = __frcp_rn(se);
        float4* op = (float4*)(g_O + base + (size_t)(nbase + nl) * NR);
        #pragma unroll
        for (int i = 0; i < 16; i++) {
            float4 o;
            o.x = (acc[i * 4]     + xa[nl * 65 + i * 4])     * inv;
            o.y = (acc[i * 4 + 1] + xa[nl * 65 + i * 4 + 1]) * inv;
            o.z = (acc[i * 4 + 2] + xa[nl * 65 + i * 4 + 2]) * inv;
            o.w = (acc[i * 4 + 3] + xa[nl * 65 + i * 4 + 3]) * inv;
            op[i] = o;
        }
    }
}

// ---------------- helper: projection with sigmoid from mrow regs through staged weight ----------------
__device__ __forceinline__ void proj_sig(const float* __restrict__ W, float* Ws,
                                         const float* mrow, float* __restrict__ outp) {
    __syncthreads();  // all prior Ws readers done
    for (int e = threadIdx.x; e < 4096; e += 128) Ws[e] = W[e];
    __syncthreads();
    float qv[64];
    #pragma unroll 4
    for (int r = 0; r < 64; r++) {
        const float4* wr = (const float4*)(Ws + r * 64);
        float z = 0.f;
        #pragma unroll
        for (int i = 0; i < 16; i++) {
            float4 w = wr[i];
            z += w.x * mrow[i * 4] + w.y * mrow[i * 4 + 1] + w.z * mrow[i * 4 + 2] + w.w * mrow[i * 4 + 3];
        }
        qv[r] = __frcp_rn(1.0f + __expf(-z));
    }
    float4* og = (float4*)outp;
    #pragma unroll
    for (int i = 0; i < 16; i++) {
        float4 v;
        v.x = qv[i * 4]; v.y = qv[i * 4 + 1]; v.z = qv[i * 4 + 2]; v.w = qv[i * 4 + 3];
        og[i] = v;
    }
}

// ---------------- transition M = silu(Ao @ O) fused with next-layer QKV projections ----------------
// grid (2, 64), 128 threads (thread = n)
__global__ void __launch_bounds__(128) k_trans(const float* __restrict__ Ao,
                                               const float* __restrict__ Wq,
                                               const float* __restrict__ Wk,
                                               const float* __restrict__ Wv) {
    __shared__ float Ws[4096];
    int b = blockIdx.y;
    int n = (blockIdx.x << 7) + threadIdx.x;
    size_t rowoff = ((size_t)b * NA + n) * NR;

    float orow[64];
    {
        const float4* og = (const float4*)(g_O + rowoff);
        #pragma unroll
        for (int i = 0; i < 16; i++) {
            float4 v = og[i];
            orow[i * 4] = v.x; orow[i * 4 + 1] = v.y; orow[i * 4 + 2] = v.z; orow[i * 4 + 3] = v.w;
        }
    }
    for (int e = threadIdx.x; e < 4096; e += 128) Ws[e] = Ao[e];
    __syncthreads();

    float mrow[64];
    #pragma unroll 4
    for (int s = 0; s < 64; s++) {
        const float4* wr = (const float4*)(Ws + s * 64);
        float z = 0.f;
        #pragma unroll
        for (int i = 0; i < 16; i++) {
            float4 w = wr[i];
            z += w.x * orow[i * 4] + w.y * orow[i * 4 + 1] + w.z * orow[i * 4 + 2] + w.w * orow[i * 4 + 3];
        }
        mrow[s] = z * __frcp_rn(1.0f + __expf(-z));  // silu
    }
    {
        float4* mg = (float4*)(g_M + rowoff);
        #pragma unroll
        for (int i = 0; i < 16; i++) {
            float4 v;
            v.x = mrow[i * 4]; v.y = mrow[i * 4 + 1]; v.z = mrow[i * 4 + 2]; v.w = mrow[i * 4 + 3];
            mg[i] = v;
        }
    }
    if (Wq == nullptr) return;  // final transition: no next-layer QKV
    proj_sig(Wq, Ws, mrow, g_Q + rowoff);
    proj_sig(Wk, Ws, mrow, g_K + rowoff);
    proj_sig(Wv, Ws, mrow, g_V + rowoff);
}

// ---------------- final: diag quadratic form + Mpp sum ----------------
__global__ void k_final(const float* __restrict__ x, float* __restrict__ out) {
    int b = blockIdx.x;
    int n = threadIdx.x;
    const float* mr = g_M + ((size_t)b * NA + n) * NR;
    float s11 = 0.f, s12 = 0.f, s21 = 0.f, s22 = 0.f, spp = 0.f;
    #pragma unroll
    for (int i = 0; i < 8; i++) {
        float a;
        a = mr[i];      s11 += a * a;
        a = mr[8 + i];  s12 += a * a;
        a = mr[16 + i]; s21 += a * a;
        a = mr[24 + i]; s22 += a * a;
    }
    #pragma unroll
    for (int i = 32; i < 64; i++) { float a = mr[i]; spp += a * a; }

    float t = spp;
    const float* xb = x + (size_t)b * ND * NA;
    #pragma unroll
    for (int kk = 0; kk < 2; kk++) {
        int k = 2 * n + kk;
        int j = k & 3;
        int col = k >> 2;
        float q1 = xb[j * NA + col];
        float q2 = xb[j * NA + 128 + col];
        t += s11 * q1 * q1 + (s12 + s21) * q1 * q2 + s22 * q2 * q2;
    }
    __shared__ float red[8];
    for (int o = 16; o > 0; o >>= 1) t += __shfl_down_sync(0xffffffffu, t, o);
    if ((n & 31) == 0) red[n >> 5] = t;
    __syncthreads();
    if (n == 0) {
        float s = 0.f;
        #pragma unroll
        for (int i = 0; i < 8; i++) s += red[i];
        out[b] = s;
    }
}

extern "C" void kernel_launch(void* const* d_in, const int* in_sizes, int n_in,
                              void* d_out, int out_size) {
    const float* x   = (const float*)d_in[0];
    const float* L   = (const float*)d_in[1];
    const float* Aq  = (const float*)d_in[2];
    const float* Ak  = (const float*)d_in[3];
    const float* Av  = (const float*)d_in[4];
    const float* Aq1 = (const float*)d_in[5];
    const float* Ak1 = (const float*)d_in[6];
    const float* Av1 = (const float*)d_in[7];
    const float* Aq5 = (const float*)d_in[8];
    const float* Ak5 = (const float*)d_in[9];
    const float* Av5 = (const float*)d_in[10];
    const float* Ao  = (const float*)d_in[11];
    const float* Ao1 = (const float*)d_in[12];
    const float* Ao5 = (const float*)d_in[13];
    float* out = (float*)d_out;

    cudaFuncSetAttribute(k_attn, cudaFuncAttributeMaxDynamicSharedMemorySize, ATTN_SMEM);

    k_scale<<<NB, 256>>>(L);
    k_gemm1<<<dim3(2, NB, 3), 256>>>(x, Aq, Ak, Av);

    k_attn<<<dim3(2, NB), 256, ATTN_SMEM>>>();
    k_trans<<<dim3(2, NB), 128>>>(Ao, Aq1, Ak1, Av1);

    k_attn<<<dim3(2, NB), 256, ATTN_SMEM>>>();
    k_trans<<<dim3(2, NB), 128>>>(Ao1, Aq5, Ak5, Av5);

    k_attn<<<dim3(2, NB), 256, ATTN_SMEM>>>();
    k_trans<<<dim3(2, NB), 128>>>(Ao5, nullptr, nullptr, nullptr);

    k_final<<<NB, 256>>>(x, out);
}

// round 3
// speedup vs baseline: 1.7719x; 1.7719x over previous
#include <cuda_runtime.h>
#include <cuda_fp16.h>
#include <math.h>
#include <cstdint>

#define NB 64
#define ND 2048
#define NA 256
#define NR 64
#define NTOK (NB*NA)   // 16384 tokens

// ---------------- device scratch (allocation-free rule) ----------------
__device__ float g_scale[NB];
__device__ __align__(16) float g_Q[NB*NA*NR];
__device__ __align__(16) float g_K[NB*NA*NR];
__device__ __align__(16) float g_V[NB*NA*NR];
__device__ __align__(16) float g_O[NB*NA*NR];
__device__ __align__(16) float g_M[NB*NA*NR];
// fp16 hi/lo split operands for the layer-1 tensor GEMM
__device__ __align__(16) __half g_Whi[256*ND];   // rows: 0-63 Aq, 64-127 Ak, 128-191 Av
__device__ __align__(16) __half g_Wlo[256*ND];
__device__ __align__(16) __half g_Xhi[(size_t)NTOK*ND];  // token-major, K contiguous
__device__ __align__(16) __half g_Xlo[(size_t)NTOK*ND];

// ---------------- PTX helpers (sm_80-compatible path only) ----------------
__device__ __forceinline__ uint32_t smem_u32(const void* p) {
    uint32_t a;
    asm("{ .reg .u64 t; cvta.to.shared.u64 t, %1; cvt.u32.u64 %0, t; }" : "=r"(a) : "l"(p));
    return a;
}
__device__ __forceinline__ void cp16(uint32_t d, const void* s) {
    asm volatile("cp.async.cg.shared.global [%0], [%1], 16;" :: "r"(d), "l"(s));
}
__device__ __forceinline__ void ldm4(uint32_t* r, uint32_t a) {
    asm volatile("ldmatrix.sync.aligned.m8n8.x4.shared.b16 {%0,%1,%2,%3}, [%4];"
        : "=r"(r[0]), "=r"(r[1]), "=r"(r[2]), "=r"(r[3]) : "r"(a));
}
__device__ __forceinline__ void mma16816(float* d, const uint32_t* a, uint32_t b0, uint32_t b1) {
    asm volatile("mma.sync.aligned.m16n8k16.row.col.f32.f16.f16.f32 "
        "{%0,%1,%2,%3}, {%4,%5,%6,%7}, {%8,%9}, {%0,%1,%2,%3};"
        : "+f"(d[0]), "+f"(d[1]), "+f"(d[2]), "+f"(d[3])
        : "r"(a[0]), "r"(a[1]), "r"(a[2]), "r"(a[3]), "r"(b0), "r"(b1));
}

// ---------------- scale ----------------
__global__ void k_scale(const float* __restrict__ L) {
    int b = blockIdx.x;
    int tid = threadIdx.x;
    float c = (L[b * 2 * NA + tid] >= 1.0f) ? 1.0f : 0.0f;
    __shared__ float red[8];
    for (int o = 16; o > 0; o >>= 1) c += __shfl_down_sync(0xffffffffu, c, o);
    if ((tid & 31) == 0) red[tid >> 5] = c;
    __syncthreads();
    if (tid == 0) {
        float t = 0.f;
        #pragma unroll
        for (int i = 0; i < 8; i++) t += red[i];
        g_scale[b] = sqrtf(t + 1.0f);
    }
}

// ---------------- W stack -> fp16 hi/lo ----------------
__global__ void __launch_bounds__(256) k_convW(const float* __restrict__ Aq,
                                               const float* __restrict__ Ak,
                                               const float* __restrict__ Av) {
    int r = blockIdx.x;      // 0..191
    int tid = threadIdx.x;
    const float* src = (r < 64)  ? Aq + (size_t)r * ND
                     : (r < 128) ? Ak + (size_t)(r - 64) * ND
                                 : Av + (size_t)(r - 128) * ND;
    #pragma unroll
    for (int i = 0; i < 8; i++) {
        int k = tid + (i << 8);
        float a = src[k];
        __half h = __float2half_rn(a);
        __half l = __float2half_rn(a - __half2float(h));
        g_Whi[(size_t)r * ND + k] = h;
        g_Wlo[(size_t)r * ND + k] = l;
    }
}

// ---------------- x transpose + fp16 hi/lo split: [b][k][n] -> token-major [c][k] ----------------
__global__ void __launch_bounds__(256) k_convX(const float* __restrict__ x) {
    __shared__ float s[64 * 129];
    int kt = blockIdx.x, nt = blockIdx.y, b = blockIdx.z;
    int k0 = kt << 6, n0 = nt << 7;
    int tid = threadIdx.x;
    const float* xb = x + ((size_t)b * ND + k0) * NA + n0;
    #pragma unroll
    for (int i = 0; i < 8; i++) {
        int e = tid + (i << 8);
        int kk = e >> 5, n4 = (e & 31) << 2;
        float4 v = *(const float4*)&xb[(size_t)kk * NA + n4];
        float* sr = s + kk * 129 + n4;
        sr[0] = v.x; sr[1] = v.y; sr[2] = v.z; sr[3] = v.w;
    }
    __syncthreads();
    size_t cbase = (size_t)b * NA + n0;
    #pragma unroll
    for (int i = 0; i < 16; i++) {
        int e = tid + (i << 8);
        int tok = e >> 5, kk2 = (e & 31) << 1;
        float a0 = s[kk2 * 129 + tok];
        float a1 = s[(kk2 + 1) * 129 + tok];
        __half h0 = __float2half_rn(a0), h1 = __float2half_rn(a1);
        __half l0 = __float2half_rn(a0 - __half2float(h0));
        __half l1 = __float2half_rn(a1 - __half2float(h1));
        size_t off = (cbase + tok) * ND + k0 + kk2;
        __half2 hh; hh.x = h0; hh.y = h1;
        __half2 ll; ll.x = l0; ll.y = l1;
        *(__half2*)(g_Xhi + off) = hh;
        *(__half2*)(g_Xlo + off) = ll;
    }
}

// ---------------- layer-1 QKV GEMM on mma.sync (HMMA), fp16 hi/lo 3-product split ------------
// grid (3 z, 128 token-tiles), 256 threads. CTA tile: M=64 (one of Q/K/V rows) x N=128 tokens.
// K=2048 in 32 chunks of 64, double-buffered cp.async. Smem rows padded to 144B (ldmatrix
// conflict-free). A = W (hi rows 0-63, lo rows 64-127); B = X (hi rows 128-255, lo 256-383).
#define KCH     64
#define ROWB    144
#define STAGE   (384 * ROWB)          // 55296 B
#define GT_SMEM (2 * STAGE)           // 110592 B
__global__ void __launch_bounds__(256, 1) k_gemmTC() {
    extern __shared__ __align__(16) char sm[];
    uint32_t smb = smem_u32(sm);
    int tid = threadIdx.x;
    int z = blockIdx.x;               // 0=Q 1=K 2=V
    int tok0 = blockIdx.y << 7;
    int wid = tid >> 5, l = tid & 31;
    int mw = (wid & 1) << 5;          // warp m offset (0/32)
    int wn = (wid >> 1) << 5;         // warp n offset (0..96)

    const __half* Wh = g_Whi + (size_t)(z * 64) * ND;
    const __half* Wl = g_Wlo + (size_t)(z * 64) * ND;

    float acc[2][4][4];
    #pragma unroll
    for (int mi = 0; mi < 2; mi++)
        #pragma unroll
        for (int nt = 0; nt < 4; nt++)
            #pragma unroll
            for (int e = 0; e < 4; e++) acc[mi][nt][e] = 0.f;

    // per-thread ldmatrix base offsets
    uint32_t aRow = (uint32_t)(mw + (l & 15));
    uint32_t aCol = (uint32_t)((l >> 4) << 4);
    uint32_t bTok = (uint32_t)(wn + (l & 7) + ((l >> 4) << 3));
    uint32_t bCol = (uint32_t)(((l >> 3) & 1) << 4);

    auto load_stage = [&](int c, int buf) {
        uint32_t bb = smb + (uint32_t)buf * STAGE;
        int k0 = c << 6;
        #pragma unroll
        for (int i = 0; i < 12; i++) {
            int s = tid + (i << 8);          // 0..3071
            int row = s >> 3, u = s & 7;
            const __half* src;
            if (row < 64)        src = Wh + (size_t)row * ND + k0 + (u << 3);
            else if (row < 128)  src = Wl + (size_t)(row - 64) * ND + k0 + (u << 3);
            else if (row < 256)  src = g_Xhi + (size_t)(tok0 + row - 128) * ND + k0 + (u << 3);
            else                 src = g_Xlo + (size_t)(tok0 + row - 256) * ND + k0 + (u << 3);
            cp16(bb + (uint32_t)(row * ROWB + (u << 4)), src);
        }
        asm volatile("cp.async.commit_group;" ::: "memory");
    };

    load_stage(0, 0);
    for (int c = 0; c < 32; c++) {
        if (c < 31) {
            load_stage(c + 1, (c + 1) & 1);
            asm volatile("cp.async.wait_group 1;" ::: "memory");
        } else {
            asm volatile("cp.async.wait_group 0;" ::: "memory");
        }
        __syncthreads();
        uint32_t bb = smb + (uint32_t)(c & 1) * STAGE;
        uint32_t Ab = bb + aRow * ROWB + aCol;
        uint32_t Bb = bb + 128u * ROWB + bTok * ROWB + bCol;
        #pragma unroll
        for (int ks = 0; ks < 4; ks++) {
            uint32_t ko = (uint32_t)(ks << 5);
            uint32_t ah[2][4], al[2][4], bh[2][4], bl[2][4];
            #pragma unroll
            for (int mi = 0; mi < 2; mi++) {
                ldm4(ah[mi], Ab + (uint32_t)(mi * 16 * ROWB) + ko);
                ldm4(al[mi], Ab + (uint32_t)((64 + mi * 16) * ROWB) + ko);
            }
            #pragma unroll
            for (int nj = 0; nj < 2; nj++) {
                ldm4(bh[nj], Bb + (uint32_t)(nj * 16 * ROWB) + ko);
                ldm4(bl[nj], Bb + (uint32_t)((128 + nj * 16) * ROWB) + ko);
            }
            #pragma unroll
            for (int mi = 0; mi < 2; mi++)
                #pragma unroll
                for (int nj = 0; nj < 2; nj++)
                    #pragma unroll
                    for (int h = 0; h < 2; h++) {
                        float* d = acc[mi][nj * 2 + h];
                        mma16816(d, ah[mi], bh[nj][2 * h], bh[nj][2 * h + 1]);
                        mma16816(d, ah[mi], bl[nj][2 * h], bl[nj][2 * h + 1]);
                        mma16816(d, al[mi], bh[nj][2 * h], bh[nj][2 * h + 1]);
                    }
        }
        __syncthreads();
    }

    // epilogue: sigmoid + transpose via smem -> token-major fp32
    float* S = (float*)sm;                 // [128 tokens][68]
    int lr = l >> 2, lc = (l & 3) << 1;
    #pragma unroll
    for (int mi = 0; mi < 2; mi++)
        #pragma unroll
        for (int nt = 0; nt < 4; nt++) {
            int m = mw + mi * 16 + lr;
            int n = wn + nt * 8 + lc;
            float* d = acc[mi][nt];
            S[n * 68 + m]           = __frcp_rn(1.0f + __expf(-d[0]));
            S[(n + 1) * 68 + m]     = __frcp_rn(1.0f + __expf(-d[1]));
            S[n * 68 + m + 8]       = __frcp_rn(1.0f + __expf(-d[2]));
            S[(n + 1) * 68 + m + 8] = __frcp_rn(1.0f + __expf(-d[3]));
        }
    __syncthreads();
    float* gdst = ((z == 0) ? g_Q : (z == 1) ? g_K : g_V) + (size_t)tok0 * NR;
    #pragma unroll
    for (int i = 0; i < 8; i++) {
        int e = tid + (i << 8);
        int tok = e >> 4, q = e & 15;
        *(float4*)(gdst + (size_t)tok * NR + (q << 2)) = *(const float4*)(S + tok * 68 + (q << 2));
    }
}

// ---------------- attention (validated R1) ----------------
#define ATTN_SMEM ((16384 + 16384 + 128 * 65 + 128) * 4)
__global__ void __launch_bounds__(256, 1) k_attn() {
    extern __shared__ float smf[];
    float* Ks = smf;
    float* Vs = smf + 16384;
    float* xa = smf + 32768;
    float* sex = xa + 128 * 65;

    int b = blockIdx.y;
    int nbase = blockIdx.x << 7;
    int tid = threadIdx.x;
    int nl = tid & 127;
    int mh = tid >> 7;
    size_t base = (size_t)b * (NA * NR);

    const float4* Kg = (const float4*)(g_K + base);
    const float4* Vg = (const float4*)(g_V + base);
    float4* Ks4 = (float4*)Ks;
    float4* Vs4 = (float4*)Vs;
    #pragma unroll
    for (int i = 0; i < 16; i++) {
        int e = tid + (i << 8);
        Ks4[e] = Kg[e];
        Vs4[e] = Vg[e];
    }
    float q[64];
    {
        const float4* qg = (const float4*)(g_Q + base + (size_t)(nbase + nl) * NR);
        #pragma unroll
        for (int i = 0; i < 16; i++) {
            float4 v = qg[i];
            q[i * 4] = v.x; q[i * 4 + 1] = v.y; q[i * 4 + 2] = v.z; q[i * 4 + 3] = v.w;
        }
    }
    float invs = __frcp_rn(g_scale[b]);
    __syncthreads();

    float acc[64];
    #pragma unroll
    for (int i = 0; i < 64; i++) acc[i] = 0.f;
    float se = 0.f;

    int mbase = mh << 7;
    for (int m = mbase; m < mbase + 128; m++) {
        const float4* kr = (const float4*)(Ks + m * NR);
        float u = 0.f;
        #pragma unroll
        for (int i = 0; i < 16; i++) {
            float4 kv = kr[i];
            u += q[i * 4] * kv.x + q[i * 4 + 1] * kv.y + q[i * 4 + 2] * kv.z + q[i * 4 + 3] * kv.w;
        }
        float p = __expf((u - 64.0f) * invs);
        se += p;
        const float4* vr = (const float4*)(Vs + m * NR);
        #pragma unroll
        for (int i = 0; i < 16; i++) {
            float4 vv = vr[i];
            acc[i * 4]     += p * vv.x;
            acc[i * 4 + 1] += p * vv.y;
            acc[i * 4 + 2] += p * vv.z;
            acc[i * 4 + 3] += p * vv.w;
        }
    }

    if (mh) {
        #pragma unroll
        for (int i = 0; i < 64; i++) xa[nl * 65 + i] = acc[i];
        sex[nl] = se;
    }
    __syncthreads();
    if (!mh) {
        se += sex[nl];
        float inv = __frcp_rn(se);
        float4* op = (float4*)(g_O + base + (size_t)(nbase + nl) * NR);
        #pragma unroll
        for (int i = 0; i < 16; i++) {
            float4 o;
            o.x = (acc[i * 4]     + xa[nl * 65 + i * 4])     * inv;
            o.y = (acc[i * 4 + 1] + xa[nl * 65 + i * 4 + 1]) * inv;
            o.z = (acc[i * 4 + 2] + xa[nl * 65 + i * 4 + 2]) * inv;
            o.w = (acc[i * 4 + 3] + xa[nl * 65 + i * 4 + 3]) * inv;
            op[i] = o;
        }
    }
}

// ---------------- transition: silu(Ao@O) + next-layer QKV, r-split ----------------
#define TR_SMEM ((4096 + 64 * 65) * 4)
__device__ __forceinline__ void proj_sig2(const float* __restrict__ W, float* Ws,
                                          const float* mrow, int h,
                                          float* __restrict__ outp) {
    __syncthreads();
    for (int e = threadIdx.x; e < 4096; e += 128) Ws[e] = W[e];
    __syncthreads();
    #pragma unroll 2
    for (int rq = 0; rq < 8; rq++) {
        int r = (h << 5) + (rq << 2);
        float4 o;
        float* zp = &o.x;
        #pragma unroll
        for (int j = 0; j < 4; j++) {
            const float4* wr = (const float4*)(Ws + (r + j) * 64);
            float z = 0.f;
            #pragma unroll
            for (int i = 0; i < 16; i++) {
                float4 w = wr[i];
                z += w.x * mrow[i * 4] + w.y * mrow[i * 4 + 1]
                   + w.z * mrow[i * 4 + 2] + w.w * mrow[i * 4 + 3];
            }
            zp[j] = __frcp_rn(1.0f + __expf(-z));
        }
        *(float4*)(outp + r) = o;
    }
}

__global__ void __launch_bounds__(128) k_trans(const float* __restrict__ Ao,
                                               const float* __restrict__ Wq,
                                               const float* __restrict__ Wk,
                                               const float* __restrict__ Wv) {
    extern __shared__ float tsm[];
    float* Ws = tsm;              // 4096
    float* Mex = tsm + 4096;      // [64][65]
    int b = blockIdx.y;
    int nl = threadIdx.x & 63;
    int h  = threadIdx.x >> 6;
    int n = (blockIdx.x << 6) + nl;
    size_t rowoff = ((size_t)b * NA + n) * NR;

    float orow[64];
    {
        const float4* og = (const float4*)(g_O + rowoff);
        #pragma unroll
        for (int i = 0; i < 16; i++) {
            float4 v = og[i];
            orow[i * 4] = v.x; orow[i * 4 + 1] = v.y;
            orow[i * 4 + 2] = v.z; orow[i * 4 + 3] = v.w;
        }
    }
    for (int e = threadIdx.x; e < 4096; e += 128) Ws[e] = Ao[e];
    __syncthreads();

    float mp[32];
    #pragma unroll 4
    for (int i = 0; i < 32; i++) {
        int srow = (h << 5) + i;
        const float4* wr = (const float4*)(Ws + srow * 64);
        float z = 0.f;
        #pragma unroll
        for (int j = 0; j < 16; j++) {
            float4 w = wr[j];
            z += w.x * orow[j * 4] + w.y * orow[j * 4 + 1]
               + w.z * orow[j * 4 + 2] + w.w * orow[j * 4 + 3];
        }
        float m = z * __frcp_rn(1.0f + __expf(-z));
        mp[i] = m;
        Mex[nl * 65 + srow] = m;
    }
    {
        float4* mg = (float4*)(g_M + rowoff + (h << 5));
        #pragma unroll
        for (int i = 0; i < 8; i++) {
            float4 v;
            v.x = mp[i * 4]; v.y = mp[i * 4 + 1]; v.z = mp[i * 4 + 2]; v.w = mp[i * 4 + 3];
            mg[i] = v;
        }
    }
    __syncthreads();
    if (Wq == nullptr) return;

    float mrow[64];
    #pragma unroll
    for (int r = 0; r < 64; r++) mrow[r] = Mex[nl * 65 + r];

    proj_sig2(Wq, Ws, mrow, h, g_Q + rowoff);
    proj_sig2(Wk, Ws, mrow, h, g_K + rowoff);
    proj_sig2(Wv, Ws, mrow, h, g_V + rowoff);
}

// ---------------- final quadratic reduction ----------------
__global__ void k_final(const float* __restrict__ x, float* __restrict__ out) {
    int b = blockIdx.x;
    int n = threadIdx.x;
    const float* mr = g_M + ((size_t)b * NA + n) * NR;
    float s11 = 0.f, s12 = 0.f, s21 = 0.f, s22 = 0.f, spp = 0.f;
    #pragma unroll
    for (int i = 0; i < 8; i++) {
        float a;
        a = mr[i];      s11 += a * a;
        a = mr[8 + i];  s12 += a * a;
        a = mr[16 + i]; s21 += a * a;
        a = mr[24 + i]; s22 += a * a;
    }
    #pragma unroll
    for (int i = 32; i < 64; i++) { float a = mr[i]; spp += a * a; }

    float t = spp;
    const float* xb = x + (size_t)b * ND * NA;
    #pragma unroll
    for (int kk = 0; kk < 2; kk++) {
        int k = 2 * n + kk;
        int j = k & 3;
        int col = k >> 2;
        float q1 = xb[j * NA + col];
        float q2 = xb[j * NA + 128 + col];
        t += s11 * q1 * q1 + (s12 + s21) * q1 * q2 + s22 * q2 * q2;
    }
    __shared__ float red[8];
    for (int o = 16; o > 0; o >>= 1) t += __shfl_down_sync(0xffffffffu, t, o);
    if ((n & 31) == 0) red[n >> 5] = t;
    __syncthreads();
    if (n == 0) {
        float s = 0.f;
        #pragma unroll
        for (int i = 0; i < 8; i++) s += red[i];
        out[b] = s;
    }
}

extern "C" void kernel_launch(void* const* d_in, const int* in_sizes, int n_in,
                              void* d_out, int out_size) {
    const float* x   = (const float*)d_in[0];
    const float* L   = (const float*)d_in[1];
    const float* Aq  = (const float*)d_in[2];
    const float* Ak  = (const float*)d_in[3];
    const float* Av  = (const float*)d_in[4];
    const float* Aq1 = (const float*)d_in[5];
    const float* Ak1 = (const float*)d_in[6];
    const float* Av1 = (const float*)d_in[7];
    const float* Aq5 = (const float*)d_in[8];
    const float* Ak5 = (const float*)d_in[9];
    const float* Av5 = (const float*)d_in[10];
    const float* Ao  = (const float*)d_in[11];
    const float* Ao1 = (const float*)d_in[12];
    const float* Ao5 = (const float*)d_in[13];
    float* out = (float*)d_out;

    cudaFuncSetAttribute(k_attn,   cudaFuncAttributeMaxDynamicSharedMemorySize, ATTN_SMEM);
    cudaFuncSetAttribute(k_gemmTC, cudaFuncAttributeMaxDynamicSharedMemorySize, GT_SMEM);

    k_scale<<<NB, 256>>>(L);
    k_convW<<<192, 256>>>(Aq, Ak, Av);
    k_convX<<<dim3(32, 2, NB), 256>>>(x);
    k_gemmTC<<<dim3(3, 128), 256, GT_SMEM>>>();

    k_attn<<<dim3(2, NB), 256, ATTN_SMEM>>>();
    k_trans<<<dim3(4, NB), 128, TR_SMEM>>>(Ao, Aq1, Ak1, Av1);

    k_attn<<<dim3(2, NB), 256, ATTN_SMEM>>>();
    k_trans<<<dim3(4, NB), 128, TR_SMEM>>>(Ao1, Aq5, Ak5, Av5);

    k_attn<<<dim3(2, NB), 256, ATTN_SMEM>>>();
    k_trans<<<dim3(4, NB), 128, TR_SMEM>>>(Ao5, nullptr, nullptr, nullptr);

    k_final<<<NB, 256>>>(x, out);
}

// round 4
// speedup vs baseline: 1.9042x; 1.0747x over previous
#include <cuda_runtime.h>
#include <cuda_fp16.h>
#include <math.h>
#include <cstdint>

#define NB 64
#define ND 2048
#define NA 256
#define NR 64
#define NTOK (NB*NA)   // 16384 tokens

// ---------------- device scratch (allocation-free rule) ----------------
__device__ float g_scale[NB];
__device__ __align__(16) float g_Q[NB*NA*NR];
__device__ __align__(16) float g_K[NB*NA*NR];
__device__ __align__(16) float g_V[NB*NA*NR];
__device__ __align__(16) float g_O[NB*NA*NR];
__device__ __align__(16) float g_M[NB*NA*NR];
// fp16 hi/lo split operands for the layer-1 tensor GEMM
__device__ __align__(16) __half g_Whi[192*ND];   // rows: 0-63 Aq, 64-127 Ak, 128-191 Av
__device__ __align__(16) __half g_Wlo[192*ND];
__device__ __align__(16) __half g_Xhi[(size_t)NTOK*ND];  // token-major, K contiguous
__device__ __align__(16) __half g_Xlo[(size_t)NTOK*ND];

// ---------------- PTX helpers (sm_80-compatible path only) ----------------
__device__ __forceinline__ uint32_t smem_u32(const void* p) {
    uint32_t a;
    asm("{ .reg .u64 t; cvta.to.shared.u64 t, %1; cvt.u32.u64 %0, t; }" : "=r"(a) : "l"(p));
    return a;
}
__device__ __forceinline__ void cp16(uint32_t d, const void* s) {
    asm volatile("cp.async.cg.shared.global [%0], [%1], 16;" :: "r"(d), "l"(s));
}
__device__ __forceinline__ void ldm4(uint32_t* r, uint32_t a) {
    asm volatile("ldmatrix.sync.aligned.m8n8.x4.shared.b16 {%0,%1,%2,%3}, [%4];"
        : "=r"(r[0]), "=r"(r[1]), "=r"(r[2]), "=r"(r[3]) : "r"(a));
}
__device__ __forceinline__ void mma16816(float* d, const uint32_t* a, uint32_t b0, uint32_t b1) {
    asm volatile("mma.sync.aligned.m16n8k16.row.col.f32.f16.f16.f32 "
        "{%0,%1,%2,%3}, {%4,%5,%6,%7}, {%8,%9}, {%0,%1,%2,%3};"
        : "+f"(d[0]), "+f"(d[1]), "+f"(d[2]), "+f"(d[3])
        : "r"(a[0]), "r"(a[1]), "r"(a[2]), "r"(a[3]), "r"(b0), "r"(b1));
}

// ---------------- scale ----------------
__global__ void k_scale(const float* __restrict__ L) {
    int b = blockIdx.x;
    int tid = threadIdx.x;
    float c = (L[b * 2 * NA + tid] >= 1.0f) ? 1.0f : 0.0f;
    __shared__ float red[8];
    for (int o = 16; o > 0; o >>= 1) c += __shfl_down_sync(0xffffffffu, c, o);
    if ((tid & 31) == 0) red[tid >> 5] = c;
    __syncthreads();
    if (tid == 0) {
        float t = 0.f;
        #pragma unroll
        for (int i = 0; i < 8; i++) t += red[i];
        g_scale[b] = sqrtf(t + 1.0f);
    }
}

// ---------------- W stack -> fp16 hi/lo ----------------
__global__ void __launch_bounds__(256) k_convW(const float* __restrict__ Aq,
                                               const float* __restrict__ Ak,
                                               const float* __restrict__ Av) {
    int r = blockIdx.x;      // 0..191
    int tid = threadIdx.x;
    const float* src = (r < 64)  ? Aq + (size_t)r * ND
                     : (r < 128) ? Ak + (size_t)(r - 64) * ND
                                 : Av + (size_t)(r - 128) * ND;
    #pragma unroll
    for (int i = 0; i < 8; i++) {
        int k = tid + (i << 8);
        float a = src[k];
        __half h = __float2half_rn(a);
        __half l = __float2half_rn(a - __half2float(h));
        g_Whi[(size_t)r * ND + k] = h;
        g_Wlo[(size_t)r * ND + k] = l;
    }
}

// ---------------- x transpose + fp16 hi/lo split: [b][k][n] -> token-major [c][k] ----------------
__global__ void __launch_bounds__(256) k_convX(const float* __restrict__ x) {
    __shared__ float s[64 * 129];
    int kt = blockIdx.x, nt = blockIdx.y, b = blockIdx.z;
    int k0 = kt << 6, n0 = nt << 7;
    int tid = threadIdx.x;
    const float* xb = x + ((size_t)b * ND + k0) * NA + n0;
    #pragma unroll
    for (int i = 0; i < 8; i++) {
        int e = tid + (i << 8);
        int kk = e >> 5, n4 = (e & 31) << 2;
        float4 v = *(const float4*)&xb[(size_t)kk * NA + n4];
        float* sr = s + kk * 129 + n4;
        sr[0] = v.x; sr[1] = v.y; sr[2] = v.z; sr[3] = v.w;
    }
    __syncthreads();
    size_t cbase = (size_t)b * NA + n0;
    #pragma unroll
    for (int i = 0; i < 16; i++) {
        int e = tid + (i << 8);
        int tok = e >> 5, kk2 = (e & 31) << 1;
        float a0 = s[kk2 * 129 + tok];
        float a1 = s[(kk2 + 1) * 129 + tok];
        __half h0 = __float2half_rn(a0), h1 = __float2half_rn(a1);
        __half l0 = __float2half_rn(a0 - __half2float(h0));
        __half l1 = __float2half_rn(a1 - __half2float(h1));
        size_t off = (cbase + tok) * ND + k0 + kk2;
        __half2 hh; hh.x = h0; hh.y = h1;
        __half2 ll; ll.x = l0; ll.y = l1;
        *(__half2*)(g_Xhi + off) = hh;
        *(__half2*)(g_Xlo + off) = ll;
    }
}

// ---------------- fused layer-1 QKV GEMM on mma.sync: M=192 (Q|K|V) x N=128 tokens per CTA ----
// grid (128 token-tiles), 256 threads (8 warps, 4m x 2n, warp tile 48x64). K=2048, chunks of 64,
// double-buffered cp.async. Smem rows 144B (ldmatrix conflict-free).
// Smem rows: 0-191 Whi, 192-383 Wlo, 384-511 Xhi(tokens), 512-639 Xlo.
#define ROWB    144
#define STAGE   (640 * ROWB)          // 92160 B
#define GT_SMEM (2 * STAGE)           // 184320 B
__global__ void __launch_bounds__(256, 1) k_gemmTC() {
    extern __shared__ __align__(16) char sm[];
    uint32_t smb = smem_u32(sm);
    int tid = threadIdx.x;
    int tok0 = blockIdx.x << 7;
    int wid = tid >> 5, l = tid & 31;
    int mbase = (wid >> 1) * 48;      // 0,48,96,144
    int nbase = (wid & 1) << 6;       // 0,64

    float acc[3][8][4];
    #pragma unroll
    for (int mi = 0; mi < 3; mi++)
        #pragma unroll
        for (int nt = 0; nt < 8; nt++)
            #pragma unroll
            for (int e = 0; e < 4; e++) acc[mi][nt][e] = 0.f;

    // per-thread ldmatrix offsets (within a stage)
    uint32_t aOff = (uint32_t)((mbase + (l & 15)) * ROWB + ((l >> 4) << 4));
    uint32_t bOff = (uint32_t)((384 + nbase + (l & 7) + ((l >> 4) << 3)) * ROWB
                               + (((l >> 3) & 1) << 4));

    auto load_stage = [&](int c, int buf) {
        uint32_t bb = smb + (uint32_t)buf * STAGE;
        int k0 = c << 6;
        #pragma unroll
        for (int i = 0; i < 20; i++) {
            int s = tid + (i << 8);          // 0..5119
            int row = s >> 3, u = s & 7;
            const __half* src;
            if (row < 192)       src = g_Whi + (size_t)row * ND + k0 + (u << 3);
            else if (row < 384)  src = g_Wlo + (size_t)(row - 192) * ND + k0 + (u << 3);
            else if (row < 512)  src = g_Xhi + (size_t)(tok0 + row - 384) * ND + k0 + (u << 3);
            else                 src = g_Xlo + (size_t)(tok0 + row - 512) * ND + k0 + (u << 3);
            cp16(bb + (uint32_t)(row * ROWB + (u << 4)), src);
        }
        asm volatile("cp.async.commit_group;" ::: "memory");
    };

    load_stage(0, 0);
    for (int c = 0; c < 32; c++) {
        if (c < 31) {
            load_stage(c + 1, (c + 1) & 1);
            asm volatile("cp.async.wait_group 1;" ::: "memory");
        } else {
            asm volatile("cp.async.wait_group 0;" ::: "memory");
        }
        __syncthreads();
        uint32_t bb = smb + (uint32_t)(c & 1) * STAGE;
        uint32_t Ah = bb + aOff;                       // Whi
        uint32_t Al = Ah + 192u * ROWB;                // Wlo
        uint32_t Bh = bb + bOff;                       // Xhi
        uint32_t Bl = Bh + 128u * ROWB;                // Xlo
        #pragma unroll
        for (int ks = 0; ks < 4; ks++) {
            uint32_t ko = (uint32_t)(ks << 5);
            uint32_t ah[3][4], al[3][4], bh[4][4], bl[4][4];
            #pragma unroll
            for (int mi = 0; mi < 3; mi++) {
                ldm4(ah[mi], Ah + (uint32_t)(mi * 16 * ROWB) + ko);
                ldm4(al[mi], Al + (uint32_t)(mi * 16 * ROWB) + ko);
            }
            #pragma unroll
            for (int nj = 0; nj < 4; nj++) {
                ldm4(bh[nj], Bh + (uint32_t)(nj * 16 * ROWB) + ko);
                ldm4(bl[nj], Bl + (uint32_t)(nj * 16 * ROWB) + ko);
            }
            #pragma unroll
            for (int mi = 0; mi < 3; mi++)
                #pragma unroll
                for (int nj = 0; nj < 4; nj++)
                    #pragma unroll
                    for (int h = 0; h < 2; h++) {
                        float* d = acc[mi][nj * 2 + h];
                        mma16816(d, ah[mi], bh[nj][2 * h], bh[nj][2 * h + 1]);
                        mma16816(d, ah[mi], bl[nj][2 * h], bl[nj][2 * h + 1]);
                        mma16816(d, al[mi], bh[nj][2 * h], bh[nj][2 * h + 1]);
                    }
        }
        __syncthreads();
    }

    // epilogue: sigmoid + transpose via smem -> token-major fp32 (reuse stage smem)
    float* S = (float*)sm;                 // [128 tokens][196]
    int lr = l >> 2, lc = (l & 3) << 1;
    #pragma unroll
    for (int mi = 0; mi < 3; mi++)
        #pragma unroll
        for (int nj = 0; nj < 4; nj++)
            #pragma unroll
            for (int h = 0; h < 2; h++) {
                int m = mbase + mi * 16 + lr;
                int n = nbase + nj * 16 + h * 8 + lc;
                float* d = acc[mi][nj * 2 + h];
                S[n * 196 + m]           = __frcp_rn(1.0f + __expf(-d[0]));
                S[(n + 1) * 196 + m]     = __frcp_rn(1.0f + __expf(-d[1]));
                S[n * 196 + m + 8]       = __frcp_rn(1.0f + __expf(-d[2]));
                S[(n + 1) * 196 + m + 8] = __frcp_rn(1.0f + __expf(-d[3]));
            }
    __syncthreads();
    #pragma unroll
    for (int i = 0; i < 24; i++) {
        int e = tid + (i << 8);           // 0..6143
        int tok = e / 48, q = e - tok * 48;
        float4 v = *(const float4*)(S + tok * 196 + (q << 2));
        float* dst = (q < 16) ? g_Q : (q < 32) ? g_K : g_V;
        int qq = q - ((q < 16) ? 0 : (q < 32) ? 16 : 32);
        *(float4*)(dst + (size_t)(tok0 + tok) * NR + (qq << 2)) = v;
    }
}

// ---------------- attention (validated) ----------------
#define ATTN_SMEM ((16384 + 16384 + 128 * 65 + 128) * 4)
__global__ void __launch_bounds__(256, 1) k_attn() {
    extern __shared__ float smf[];
    float* Ks = smf;
    float* Vs = smf + 16384;
    float* xa = smf + 32768;
    float* sex = xa + 128 * 65;

    int b = blockIdx.y;
    int nbase = blockIdx.x << 7;
    int tid = threadIdx.x;
    int nl = tid & 127;
    int mh = tid >> 7;
    size_t base = (size_t)b * (NA * NR);

    const float4* Kg = (const float4*)(g_K + base);
    const float4* Vg = (const float4*)(g_V + base);
    float4* Ks4 = (float4*)Ks;
    float4* Vs4 = (float4*)Vs;
    #pragma unroll
    for (int i = 0; i < 16; i++) {
        int e = tid + (i << 8);
        Ks4[e] = Kg[e];
        Vs4[e] = Vg[e];
    }
    float q[64];
    {
        const float4* qg = (const float4*)(g_Q + base + (size_t)(nbase + nl) * NR);
        #pragma unroll
        for (int i = 0; i < 16; i++) {
            float4 v = qg[i];
            q[i * 4] = v.x; q[i * 4 + 1] = v.y; q[i * 4 + 2] = v.z; q[i * 4 + 3] = v.w;
        }
    }
    float invs = __frcp_rn(g_scale[b]);
    __syncthreads();

    float acc[64];
    #pragma unroll
    for (int i = 0; i < 64; i++) acc[i] = 0.f;
    float se = 0.f;

    int mbase = mh << 7;
    for (int m = mbase; m < mbase + 128; m++) {
        const float4* kr = (const float4*)(Ks + m * NR);
        float u = 0.f;
        #pragma unroll
        for (int i = 0; i < 16; i++) {
            float4 kv = kr[i];
            u += q[i * 4] * kv.x + q[i * 4 + 1] * kv.y + q[i * 4 + 2] * kv.z + q[i * 4 + 3] * kv.w;
        }
        float p = __expf((u - 64.0f) * invs);
        se += p;
        const float4* vr = (const float4*)(Vs + m * NR);
        #pragma unroll
        for (int i = 0; i < 16; i++) {
            float4 vv = vr[i];
            acc[i * 4]     += p * vv.x;
            acc[i * 4 + 1] += p * vv.y;
            acc[i * 4 + 2] += p * vv.z;
            acc[i * 4 + 3] += p * vv.w;
        }
    }

    if (mh) {
        #pragma unroll
        for (int i = 0; i < 64; i++) xa[nl * 65 + i] = acc[i];
        sex[nl] = se;
    }
    __syncthreads();
    if (!mh) {
        se += sex[nl];
        float inv = __frcp_rn(se);
        float4* op = (float4*)(g_O + base + (size_t)(nbase + nl) * NR);
        #pragma unroll
        for (int i = 0; i < 16; i++) {
            float4 o;
            o.x = (acc[i * 4]     + xa[nl * 65 + i * 4])     * inv;
            o.y = (acc[i * 4 + 1] + xa[nl * 65 + i * 4 + 1]) * inv;
            o.z = (acc[i * 4 + 2] + xa[nl * 65 + i * 4 + 2]) * inv;
            o.w = (acc[i * 4 + 3] + xa[nl * 65 + i * 4 + 3]) * inv;
            op[i] = o;
        }
    }
}

// ---------------- transition: silu(Ao@O) + next-layer QKV, r-split ----------------
#define TR_SMEM ((4096 + 64 * 65) * 4)
__device__ __forceinline__ void proj_sig2(const float* __restrict__ W, float* Ws,
                                          const float* mrow, int h,
                                          float* __restrict__ outp) {
    __syncthreads();
    for (int e = threadIdx.x; e < 4096; e += 128) Ws[e] = W[e];
    __syncthreads();
    #pragma unroll 2
    for (int rq = 0; rq < 8; rq++) {
        int r = (h << 5) + (rq << 2);
        float4 o;
        float* zp = &o.x;
        #pragma unroll
        for (int j = 0; j < 4; j++) {
            const float4* wr = (const float4*)(Ws + (r + j) * 64);
            float z = 0.f;
            #pragma unroll
            for (int i = 0; i < 16; i++) {
                float4 w = wr[i];
                z += w.x * mrow[i * 4] + w.y * mrow[i * 4 + 1]
                   + w.z * mrow[i * 4 + 2] + w.w * mrow[i * 4 + 3];
            }
            zp[j] = __frcp_rn(1.0f + __expf(-z));
        }
        *(float4*)(outp + r) = o;
    }
}

__global__ void __launch_bounds__(128) k_trans(const float* __restrict__ Ao,
                                               const float* __restrict__ Wq,
                                               const float* __restrict__ Wk,
                                               const float* __restrict__ Wv) {
    extern __shared__ float tsm[];
    float* Ws = tsm;              // 4096
    float* Mex = tsm + 4096;      // [64][65]
    int b = blockIdx.y;
    int nl = threadIdx.x & 63;
    int h  = threadIdx.x >> 6;
    int n = (blockIdx.x << 6) + nl;
    size_t rowoff = ((size_t)b * NA + n) * NR;

    float orow[64];
    {
        const float4* og = (const float4*)(g_O + rowoff);
        #pragma unroll
        for (int i = 0; i < 16; i++) {
            float4 v = og[i];
            orow[i * 4] = v.x; orow[i * 4 + 1] = v.y;
            orow[i * 4 + 2] = v.z; orow[i * 4 + 3] = v.w;
        }
    }
    for (int e = threadIdx.x; e < 4096; e += 128) Ws[e] = Ao[e];
    __syncthreads();

    float mp[32];
    #pragma unroll 4
    for (int i = 0; i < 32; i++) {
        int srow = (h << 5) + i;
        const float4* wr = (const float4*)(Ws + srow * 64);
        float z = 0.f;
        #pragma unroll
        for (int j = 0; j < 16; j++) {
            float4 w = wr[j];
            z += w.x * orow[j * 4] + w.y * orow[j * 4 + 1]
               + w.z * orow[j * 4 + 2] + w.w * orow[j * 4 + 3];
        }
        float m = z * __frcp_rn(1.0f + __expf(-z));
        mp[i] = m;
        Mex[nl * 65 + srow] = m;
    }
    {
        float4* mg = (float4*)(g_M + rowoff + (h << 5));
        #pragma unroll
        for (int i = 0; i < 8; i++) {
            float4 v;
            v.x = mp[i * 4]; v.y = mp[i * 4 + 1]; v.z = mp[i * 4 + 2]; v.w = mp[i * 4 + 3];
            mg[i] = v;
        }
    }
    __syncthreads();
    if (Wq == nullptr) return;

    float mrow[64];
    #pragma unroll
    for (int r = 0; r < 64; r++) mrow[r] = Mex[nl * 65 + r];

    proj_sig2(Wq, Ws, mrow, h, g_Q + rowoff);
    proj_sig2(Wk, Ws, mrow, h, g_K + rowoff);
    proj_sig2(Wv, Ws, mrow, h, g_V + rowoff);
}

// ---------------- final quadratic reduction ----------------
__global__ void k_final(const float* __restrict__ x, float* __restrict__ out) {
    int b = blockIdx.x;
    int n = threadIdx.x;
    const float* mr = g_M + ((size_t)b * NA + n) * NR;
    float s11 = 0.f, s12 = 0.f, s21 = 0.f, s22 = 0.f, spp = 0.f;
    #pragma unroll
    for (int i = 0; i < 8; i++) {
        float a;
        a = mr[i];      s11 += a * a;
        a = mr[8 + i];  s12 += a * a;
        a = mr[16 + i]; s21 += a * a;
        a = mr[24 + i]; s22 += a * a;
    }
    #pragma unroll
    for (int i = 32; i < 64; i++) { float a = mr[i]; spp += a * a; }

    float t = spp;
    const float* xb = x + (size_t)b * ND * NA;
    #pragma unroll
    for (int kk = 0; kk < 2; kk++) {
        int k = 2 * n + kk;
        int j = k & 3;
        int col = k >> 2;
        float q1 = xb[j * NA + col];
        float q2 = xb[j * NA + 128 + col];
        t += s11 * q1 * q1 + (s12 + s21) * q1 * q2 + s22 * q2 * q2;
    }
    __shared__ float red[8];
    for (int o = 16; o > 0; o >>= 1) t += __shfl_down_sync(0xffffffffu, t, o);
    if ((n & 31) == 0) red[n >> 5] = t;
    __syncthreads();
    if (n == 0) {
        float s = 0.f;
        #pragma unroll
        for (int i = 0; i < 8; i++) s += red[i];
        out[b] = s;
    }
}

extern "C" void kernel_launch(void* const* d_in, const int* in_sizes, int n_in,
                              void* d_out, int out_size) {
    const float* x   = (const float*)d_in[0];
    const float* L   = (const float*)d_in[1];
    const float* Aq  = (const float*)d_in[2];
    const float* Ak  = (const float*)d_in[3];
    const float* Av  = (const float*)d_in[4];
    const float* Aq1 = (const float*)d_in[5];
    const float* Ak1 = (const float*)d_in[6];
    const float* Av1 = (const float*)d_in[7];
    const float* Aq5 = (const float*)d_in[8];
    const float* Ak5 = (const float*)d_in[9];
    const float* Av5 = (const float*)d_in[10];
    const float* Ao  = (const float*)d_in[11];
    const float* Ao1 = (const float*)d_in[12];
    const float* Ao5 = (const float*)d_in[13];
    float* out = (float*)d_out;

    cudaFuncSetAttribute(k_attn,   cudaFuncAttributeMaxDynamicSharedMemorySize, ATTN_SMEM);
    cudaFuncSetAttribute(k_gemmTC, cudaFuncAttributeMaxDynamicSharedMemorySize, GT_SMEM);

    k_scale<<<NB, 256>>>(L);
    k_convW<<<192, 256>>>(Aq, Ak, Av);
    k_convX<<<dim3(32, 2, NB), 256>>>(x);
    k_gemmTC<<<128, 256, GT_SMEM>>>();

    k_attn<<<dim3(2, NB), 256, ATTN_SMEM>>>();
    k_trans<<<dim3(4, NB), 128, TR_SMEM>>>(Ao, Aq1, Ak1, Av1);

    k_attn<<<dim3(2, NB), 256, ATTN_SMEM>>>();
    k_trans<<<dim3(4, NB), 128, TR_SMEM>>>(Ao1, Aq5, Ak5, Av5);

    k_attn<<<dim3(2, NB), 256, ATTN_SMEM>>>();
    k_trans<<<dim3(4, NB), 128, TR_SMEM>>>(Ao5, nullptr, nullptr, nullptr);

    k_final<<<NB, 256>>>(x, out);
}